// round 5
// baseline (speedup 1.0000x reference)
#include <cuda_runtime.h>
#include <cuda_fp16.h>

#define DD 128
#define MAXN 40000
#define MAXE 600000

// ---------------- device scratch (allocation-free rule) ----------------
__device__ float g_Ah[MAXN * DD];
__device__ float g_Bh[MAXN * DD];
__device__ float g_Dh[MAXN * DD];
__device__ float g_Eh[MAXN * DD];
__device__ int   g_cnt[MAXN];
__device__ int   g_off[MAXN + 1];
__device__ int   g_cur[MAXN];
__device__ int   g_perm[MAXE];
// 5 transposed fp16 weights, pre-swizzled (blocked layout below)
__device__ __align__(16) unsigned char g_Wh[5 * 32768];

// ---------------- smem layouts ----------------
// edge: W 32KB | A 32KB | C 128x68 f32 (34816B)  -> 100352B, 2 CTAs/SM
#define ESM_W 0
#define ESM_A 32768
#define ESM_C 65536
#define CSTR  68
#define ESM_REQ (65536 + 128 * CSTR * 4)
// node: W 32KB | A 32KB -> 65536B
#define NSM_W 0
#define NSM_A 32768
#define NSM_REQ 65536

// ---------------- helpers ----------------
static __device__ __forceinline__ unsigned smem_u32(const void* p) {
    unsigned a;
    asm("{ .reg .u64 t; cvta.to.shared.u64 t, %1; cvt.u32.u64 %0, t; }" : "=r"(a) : "l"(p));
    return a;
}
// blocked swizzled layout for a 128-row x 128-halfword-col tile
static __device__ __forceinline__ unsigned bsw(int row, int col) {
    unsigned off = (unsigned)((((row >> 3) + ((col >> 6) << 4)) << 10)
                              + ((row & 7) << 7) + ((col & 63) << 1));
    return off ^ ((off >> 3) & 0x70);
}
static __device__ __forceinline__ void ldsm_x4(unsigned& r0, unsigned& r1,
                                               unsigned& r2, unsigned& r3, unsigned addr) {
    asm volatile("ldmatrix.sync.aligned.m8n8.x4.shared.b16 {%0,%1,%2,%3}, [%4];"
                 : "=r"(r0), "=r"(r1), "=r"(r2), "=r"(r3) : "r"(addr));
}
static __device__ __forceinline__ void mma_fp16(float c[4], unsigned a0, unsigned a1,
                                                unsigned a2, unsigned a3,
                                                unsigned b0, unsigned b1) {
    asm volatile("mma.sync.aligned.m16n8k16.row.col.f32.f16.f16.f32 "
                 "{%0,%1,%2,%3}, {%4,%5,%6,%7}, {%8,%9}, {%0,%1,%2,%3};"
                 : "+f"(c[0]), "+f"(c[1]), "+f"(c[2]), "+f"(c[3])
                 : "r"(a0), "r"(a1), "r"(a2), "r"(a3), "r"(b0), "r"(b1));
}

// fp32 tile -> fp16, written straight into swizzled smem. 256 threads.
template<bool SCALE>
static __device__ __forceinline__ void load_convert_A(
        const float* __restrict__ X, const float* __restrict__ norm,
        int row0, int M, unsigned char* A) {
    int t = threadIdx.x;
    #pragma unroll
    for (int it = 0; it < 16; it++) {
        int f = t + it * 256;
        int row = f >> 5;
        int col0 = (f & 31) * 4;
        int gr = row0 + row;
        float4 v = make_float4(0.f, 0.f, 0.f, 0.f);
        if (gr < M) {
            v = __ldg((const float4*)(X + (size_t)gr * DD + col0));
            if (SCALE) {
                float nm = __ldg(norm + gr);
                v.x *= nm; v.y *= nm; v.z *= nm; v.w *= nm;
            }
        }
        unsigned p0, p1;
        asm("cvt.rn.f16x2.f32 %0, %1, %2;" : "=r"(p0) : "f"(v.y), "f"(v.x));
        asm("cvt.rn.f16x2.f32 %0, %1, %2;" : "=r"(p1) : "f"(v.w), "f"(v.z));
        *(uint2*)(A + bsw(row, col0)) = make_uint2(p0, p1);
    }
}

// ---------------- fp16 single-pass GEMM: 128x128x128, 8 warps, warp = 16 rows ----------------
static __device__ __forceinline__ void gemm_fp16_tile(
        const unsigned char* smA, const unsigned char* smW, float acc[16][4]) {
    unsigned aB = smem_u32(smA), wB = smem_u32(smW);
    int tid = threadIdx.x, lane = tid & 31, w = tid >> 5;
    int lr = lane & 7, m = lane >> 3;
    int aRow = w * 16 + (m & 1) * 8 + lr;
    int aCol = (m >> 1) * 8;
    int bRow = (m >> 1) * 8 + lr;
    int bCol = (m & 1) * 8;

    #pragma unroll
    for (int n8 = 0; n8 < 16; n8++)
        #pragma unroll
        for (int q = 0; q < 4; q++) acc[n8][q] = 0.f;

    #pragma unroll
    for (int kk = 0; kk < 8; kk++) {
        int k0 = kk * 16;
        unsigned a0, a1, a2, a3;
        ldsm_x4(a0, a1, a2, a3, aB + bsw(aRow, k0 + aCol));
        #pragma unroll
        for (int nt = 0; nt < 8; nt++) {
            unsigned b0, b1, b2, b3;
            ldsm_x4(b0, b1, b2, b3, wB + bsw(bRow + nt * 16, k0 + bCol));
            mma_fp16(acc[nt * 2],     a0, a1, a2, a3, b0, b1);
            mma_fp16(acc[nt * 2 + 1], a0, a1, a2, a3, b2, b3);
        }
    }
}

// ---------------- prep: zero histogram + transpose/convert/swizzle weights ----------------
__global__ void prep_kernel(const float* __restrict__ Wa, const float* __restrict__ Wb,
                            const float* __restrict__ Wc, const float* __restrict__ Wd,
                            const float* __restrict__ We, int Nn) {
    int idx = blockIdx.x * blockDim.x + threadIdx.x;
    if (idx < Nn) g_cnt[idx] = 0;
    if (idx < 5 * 16384) {
        int mm = idx >> 14;
        int rem = idx & 16383;
        int n = rem >> 7, k = rem & 127;
        const float* W = (mm == 0) ? Wa : (mm == 1) ? Wb : (mm == 2) ? Wc : (mm == 3) ? Wd : We;
        float v = W[k * DD + n];                 // transpose: Wt[n][k] = W[k][n]
        *(__half*)(g_Wh + mm * 32768 + bsw(n, k)) = __float2half_rn(v);
    }
}

// ---------------- counting sort by dst ----------------
__global__ void hist_kernel(const int* __restrict__ dst, int E) {
    int idx = blockIdx.x * blockDim.x + threadIdx.x;
    if (idx < E) atomicAdd(&g_cnt[__ldg(dst + idx)], 1);
}

__global__ void scan_kernel(int Nn) {
    __shared__ int ss[1024];
    const int CH = 40;                 // 1024*40 = 40960 >= Nn
    int t = threadIdx.x;
    int base = t * CH;
    int s = 0;
    for (int i = 0; i < CH; i++)
        s += (base + i < Nn) ? g_cnt[base + i] : 0;
    ss[t] = s;
    __syncthreads();
    for (int d = 1; d < 1024; d <<= 1) {
        int v = (t >= d) ? ss[t - d] : 0;
        __syncthreads();
        ss[t] += v;
        __syncthreads();
    }
    int run = ss[t] - s;               // exclusive prefix
    for (int i = 0; i < CH; i++) {
        if (base + i < Nn) {
            g_off[base + i] = run;
            g_cur[base + i] = run;
            run += g_cnt[base + i];
        }
    }
    if (t == 1023) g_off[Nn] = ss[1023];
}

__global__ void scatter_kernel(const int* __restrict__ dst, int E) {
    int idx = blockIdx.x * blockDim.x + threadIdx.x;
    if (idx < E) {
        int pos = atomicAdd(&g_cur[__ldg(dst + idx)], 1);
        g_perm[pos] = idx;
    }
}

// ---------------- node GEMMs: out_y = (h*norm)@W_y + b_y ----------------
__global__ __launch_bounds__(256, 2) void node_mma_kernel(
        const float* __restrict__ h, const float* __restrict__ norm,
        const float* __restrict__ ba, const float* __restrict__ bb,
        const float* __restrict__ bd, const float* __restrict__ be, int M) {
    extern __shared__ unsigned char sm[];
    int tid = threadIdx.x;
    int y = blockIdx.y;
    int widx = (y == 0) ? 0 : (y == 1) ? 1 : (y == 2) ? 3 : 4;   // a,b,d,e
    float* out        = (y == 0) ? g_Ah : (y == 1) ? g_Bh : (y == 2) ? g_Dh : g_Eh;
    const float* bias = (y == 0) ? ba   : (y == 1) ? bb   : (y == 2) ? bd   : be;
    int row0 = blockIdx.x * 128;

    {
        const uint4* s = (const uint4*)(g_Wh + widx * 32768);
        uint4* d = (uint4*)(sm + NSM_W);
        #pragma unroll
        for (int i = tid; i < 2048; i += 256) d[i] = __ldg(s + i);
    }
    load_convert_A<true>(h, norm, row0, M, sm + NSM_A);
    __syncthreads();

    float acc[16][4];
    gemm_fp16_tile(sm + NSM_A, sm + NSM_W, acc);

    int lane = tid & 31, w = tid >> 5;
    int r0 = row0 + w * 16 + (lane >> 2);
    int cp = 2 * (lane & 3);
    #pragma unroll
    for (int n8 = 0; n8 < 16; n8++) {
        int c = n8 * 8 + cp;
        float2 bv = __ldg((const float2*)(bias + c));
        if (r0 < M)
            *(float2*)(out + (size_t)r0 * DD + c) =
                make_float2(acc[n8][0] + bv.x, acc[n8][1] + bv.y);
        if (r0 + 8 < M)
            *(float2*)(out + (size_t)(r0 + 8) * DD + c) =
                make_float2(acc[n8][2] + bv.x, acc[n8][3] + bv.y);
    }
}

// ---------------- edge kernel: e_ij = Ce + bc + Dh[src] + Eh[dst]; write only ----------------
static __device__ __forceinline__ void edge_epilogue_half(
        const unsigned char* sm, int half, int tile, int E,
        const float* __restrict__ bc, const int* __restrict__ src,
        const int* __restrict__ dst, float* __restrict__ out_e) {
    int t = threadIdx.x;
    int row = t & 127;
    int coff = (t >> 7) * 32;               // 32 cols per thread within the 64-col half
    int er = tile * 128 + row;
    if (er >= E) return;
    int s = __ldg(src + er), d = __ldg(dst + er);
    const float* C = (const float*)(sm + ESM_C) + row * CSTR;
    const float* Dhp = g_Dh + (size_t)s * DD;
    const float* Ehp = g_Eh + (size_t)d * DD;
    float* eop = out_e + (size_t)er * DD;

    #pragma unroll
    for (int i = 0; i < 8; i++) {
        int cl = coff + i * 4;
        int c = half * 64 + cl;
        float4 cx = *(const float4*)(C + cl);
        float4 b  = __ldg((const float4*)(bc + c));
        float4 dh = __ldg((const float4*)(Dhp + c));
        float4 eh = __ldg((const float4*)(Ehp + c));
        float4 x;
        x.x = cx.x + b.x + dh.x + eh.x;
        x.y = cx.y + b.y + dh.y + eh.y;
        x.z = cx.z + b.z + dh.z + eh.z;
        x.w = cx.w + b.w + dh.w + eh.w;
        *(float4*)(eop + c) = x;
    }
}

__global__ __launch_bounds__(256, 2) void edge_mma_kernel(
        const float* __restrict__ e, const float* __restrict__ bc,
        const int* __restrict__ src, const int* __restrict__ dst,
        float* __restrict__ out_e, int E) {
    extern __shared__ unsigned char sm[];
    int tid = threadIdx.x;
    {   // Wc (index 2), loaded once per persistent CTA
        const uint4* s = (const uint4*)(g_Wh + 2 * 32768);
        uint4* d = (uint4*)(sm + ESM_W);
        #pragma unroll
        for (int i = tid; i < 2048; i += 256) d[i] = __ldg(s + i);
    }

    int lane = tid & 31, w = tid >> 5;
    int sr0 = w * 16 + (lane >> 2);
    int scp = 2 * (lane & 3);
    float* C = (float*)(sm + ESM_C);

    int ntiles = (E + 127) >> 7;
    for (int tile = blockIdx.x; tile < ntiles; tile += gridDim.x) {
        load_convert_A<false>(e, nullptr, tile * 128, E, sm + ESM_A);
        __syncthreads();

        float acc[16][4];
        gemm_fp16_tile(sm + ESM_A, sm + ESM_W, acc);

        #pragma unroll
        for (int half = 0; half < 2; half++) {
            __syncthreads();
            #pragma unroll
            for (int k = 0; k < 8; k++) {
                int n8 = half * 8 + k;
                int cl = k * 8 + scp;
                *(float2*)(C + sr0 * CSTR + cl) = make_float2(acc[n8][0], acc[n8][1]);
                *(float2*)(C + (sr0 + 8) * CSTR + cl) = make_float2(acc[n8][2], acc[n8][3]);
            }
            __syncthreads();
            edge_epilogue_half(sm, half, tile, E, bc, src, dst, out_e);
        }
    }
}

// ---------------- aggregate + finalize: one warp per dst node, no atomics ----------------
__global__ __launch_bounds__(256) void aggregate_kernel(
        const float* __restrict__ eij, const int* __restrict__ src,
        const float* __restrict__ h, const float* __restrict__ norm,
        float* __restrict__ out_h, int Nn) {
    int node = blockIdx.x * 8 + (threadIdx.x >> 5);
    if (node >= Nn) return;
    int lane = threadIdx.x & 31;
    int beg = __ldg(&g_off[node]);
    int end = __ldg(&g_off[node + 1]);

    float4 num = make_float4(0.f, 0.f, 0.f, 0.f);
    float4 den = make_float4(0.f, 0.f, 0.f, 0.f);

    int er_next = (beg < end) ? __ldg(g_perm + beg) : 0;
    for (int k = beg; k < end; k++) {
        int er = er_next;
        if (k + 1 < end) er_next = __ldg(g_perm + k + 1);
        int s = __ldg(src + er);
        float4 x  = __ldg((const float4*)(eij + (size_t)er * DD + lane * 4));
        float4 bh = __ldg((const float4*)(g_Bh + (size_t)s * DD + lane * 4));
        float4 sg;
        sg.x = __fdividef(1.f, 1.f + __expf(-x.x));
        sg.y = __fdividef(1.f, 1.f + __expf(-x.y));
        sg.z = __fdividef(1.f, 1.f + __expf(-x.z));
        sg.w = __fdividef(1.f, 1.f + __expf(-x.w));
        num.x += sg.x * bh.x; num.y += sg.y * bh.y;
        num.z += sg.z * bh.z; num.w += sg.w * bh.w;
        den.x += sg.x; den.y += sg.y; den.z += sg.z; den.w += sg.w;
    }

    float nm = __ldg(norm + node);
    float4 r;
    if (end > beg) {
        float4 a = __ldg((const float4*)(g_Ah + (size_t)node * DD + lane * 4));
        r.x = (a.x + num.x / (den.x + 1e-6f)) * nm;
        r.y = (a.y + num.y / (den.y + 1e-6f)) * nm;
        r.z = (a.z + num.z / (den.z + 1e-6f)) * nm;
        r.w = (a.w + num.w / (den.w + 1e-6f)) * nm;
    } else {
        float4 hh = __ldg((const float4*)(h + (size_t)node * DD + lane * 4));
        float sc = nm * nm;                    // hs * norm = h * norm^2
        r = make_float4(hh.x * sc, hh.y * sc, hh.z * sc, hh.w * sc);
    }
    *(float4*)(out_h + (size_t)node * DD + lane * 4) = r;
}

// ---------------- launch ----------------
extern "C" void kernel_launch(void* const* d_in, const int* in_sizes, int n_in,
                              void* d_out, int out_size) {
    const float* h    = (const float*)d_in[0];
    const float* e    = (const float*)d_in[1];
    const float* norm = (const float*)d_in[2];
    const int*   src  = (const int*)d_in[3];
    const int*   dst  = (const int*)d_in[4];
    const float* Wa = (const float*)d_in[5],  *ba = (const float*)d_in[6];
    const float* Wb = (const float*)d_in[7],  *bb = (const float*)d_in[8];
    const float* Wc = (const float*)d_in[9],  *bc = (const float*)d_in[10];
    const float* Wd = (const float*)d_in[11], *bd = (const float*)d_in[12];
    const float* We = (const float*)d_in[13], *be = (const float*)d_in[14];

    int Nn = in_sizes[0] / DD;   // 40000
    int Ee = in_sizes[3];        // 600000

    float* out_h = (float*)d_out;
    float* out_e = out_h + (size_t)Nn * DD;

    cudaFuncSetAttribute(node_mma_kernel, cudaFuncAttributeMaxDynamicSharedMemorySize, NSM_REQ);
    cudaFuncSetAttribute(edge_mma_kernel, cudaFuncAttributeMaxDynamicSharedMemorySize, ESM_REQ);

    prep_kernel<<<(5 * 16384 + 255) / 256, 256>>>(Wa, Wb, Wc, Wd, We, Nn);
    hist_kernel<<<(Ee + 255) / 256, 256>>>(dst, Ee);
    scan_kernel<<<1, 1024>>>(Nn);
    scatter_kernel<<<(Ee + 255) / 256, 256>>>(dst, Ee);

    dim3 ngrid((Nn + 127) / 128, 4);
    node_mma_kernel<<<ngrid, 256, NSM_REQ>>>(h, norm, ba, bb, bd, be, Nn);

    edge_mma_kernel<<<296, 256, ESM_REQ>>>(e, bc, src, dst, out_e, Ee);

    aggregate_kernel<<<(Nn + 7) / 8, 256>>>(out_e, src, h, norm, out_h, Nn);
}

// round 6
// speedup vs baseline: 2.4864x; 2.4864x over previous
#include <cuda_runtime.h>
#include <cuda_fp16.h>

#define DD 128
#define MAXN 40000

// ---------------- device scratch (allocation-free rule) ----------------
__device__ float g_Ah[MAXN * DD];
__device__ float g_Bh[MAXN * DD];
__device__ float g_Dh[MAXN * DD];   // holds hs@Wd + bd + bc  (bc folded in)
__device__ float g_Eh[MAXN * DD];
__device__ float g_num[MAXN * DD];
__device__ float g_den[MAXN * DD];
// 5 transposed fp16 weights, pre-swizzled (blocked layout below)
__device__ __align__(16) unsigned char g_Wh[5 * 32768];

// ---------------- smem layouts ----------------
// edge: W 32KB | A 32KB -> 65536B, 3 CTAs/SM
#define ESM_W 0
#define ESM_A 32768
#define ESM_REQ 65536
// node: identical footprint
#define NSM_W 0
#define NSM_A 32768
#define NSM_REQ 65536

// ---------------- helpers ----------------
static __device__ __forceinline__ unsigned smem_u32(const void* p) {
    unsigned a;
    asm("{ .reg .u64 t; cvta.to.shared.u64 t, %1; cvt.u32.u64 %0, t; }" : "=r"(a) : "l"(p));
    return a;
}
// blocked swizzled layout for a 128-row x 128-halfword-col tile
static __device__ __forceinline__ unsigned bsw(int row, int col) {
    unsigned off = (unsigned)((((row >> 3) + ((col >> 6) << 4)) << 10)
                              + ((row & 7) << 7) + ((col & 63) << 1));
    return off ^ ((off >> 3) & 0x70);
}
static __device__ __forceinline__ void ldsm_x4(unsigned& r0, unsigned& r1,
                                               unsigned& r2, unsigned& r3, unsigned addr) {
    asm volatile("ldmatrix.sync.aligned.m8n8.x4.shared.b16 {%0,%1,%2,%3}, [%4];"
                 : "=r"(r0), "=r"(r1), "=r"(r2), "=r"(r3) : "r"(addr));
}
static __device__ __forceinline__ void mma_fp16(float c[4], unsigned a0, unsigned a1,
                                                unsigned a2, unsigned a3,
                                                unsigned b0, unsigned b1) {
    asm volatile("mma.sync.aligned.m16n8k16.row.col.f32.f16.f16.f32 "
                 "{%0,%1,%2,%3}, {%4,%5,%6,%7}, {%8,%9}, {%0,%1,%2,%3};"
                 : "+f"(c[0]), "+f"(c[1]), "+f"(c[2]), "+f"(c[3])
                 : "r"(a0), "r"(a1), "r"(a2), "r"(a3), "r"(b0), "r"(b1));
}
static __device__ __forceinline__ void red_add_v2(float* p, float x, float y) {
    asm volatile("red.global.add.v2.f32 [%0], {%1,%2};"
                 :: "l"(p), "f"(x), "f"(y) : "memory");
}

// fp32 tile -> fp16, written straight into swizzled smem. 256 threads.
template<bool SCALE>
static __device__ __forceinline__ void load_convert_A(
        const float* __restrict__ X, const float* __restrict__ norm,
        int row0, int M, unsigned char* A) {
    int t = threadIdx.x;
    #pragma unroll
    for (int it = 0; it < 16; it++) {
        int f = t + it * 256;
        int row = f >> 5;
        int col0 = (f & 31) * 4;
        int gr = row0 + row;
        float4 v = make_float4(0.f, 0.f, 0.f, 0.f);
        if (gr < M) {
            v = __ldg((const float4*)(X + (size_t)gr * DD + col0));
            if (SCALE) {
                float nm = __ldg(norm + gr);
                v.x *= nm; v.y *= nm; v.z *= nm; v.w *= nm;
            }
        }
        unsigned p0, p1;
        asm("cvt.rn.f16x2.f32 %0, %1, %2;" : "=r"(p0) : "f"(v.y), "f"(v.x));
        asm("cvt.rn.f16x2.f32 %0, %1, %2;" : "=r"(p1) : "f"(v.w), "f"(v.z));
        *(uint2*)(A + bsw(row, col0)) = make_uint2(p0, p1);
    }
}

// ---------------- fp16 GEMM, 64-col half: 8 warps, warp = 16 rows x 64 cols ----------------
static __device__ __forceinline__ void gemm_fp16_half(
        const unsigned char* smA, const unsigned char* smW, int half, float acc[8][4]) {
    unsigned aB = smem_u32(smA), wB = smem_u32(smW);
    int tid = threadIdx.x, lane = tid & 31, w = tid >> 5;
    int lr = lane & 7, m = lane >> 3;
    int aRow = w * 16 + (m & 1) * 8 + lr;
    int aCol = (m >> 1) * 8;
    int bRow = half * 64 + (m >> 1) * 8 + lr;
    int bCol = (m & 1) * 8;

    #pragma unroll
    for (int n8 = 0; n8 < 8; n8++)
        #pragma unroll
        for (int q = 0; q < 4; q++) acc[n8][q] = 0.f;

    #pragma unroll
    for (int kk = 0; kk < 8; kk++) {
        int k0 = kk * 16;
        unsigned a0, a1, a2, a3;
        ldsm_x4(a0, a1, a2, a3, aB + bsw(aRow, k0 + aCol));
        #pragma unroll
        for (int nt = 0; nt < 4; nt++) {
            unsigned b0, b1, b2, b3;
            ldsm_x4(b0, b1, b2, b3, wB + bsw(bRow + nt * 16, k0 + bCol));
            mma_fp16(acc[nt * 2],     a0, a1, a2, a3, b0, b1);
            mma_fp16(acc[nt * 2 + 1], a0, a1, a2, a3, b2, b3);
        }
    }
}

// ---------------- prep: transpose/convert/swizzle weights ----------------
__global__ void prep_kernel(const float* __restrict__ Wa, const float* __restrict__ Wb,
                            const float* __restrict__ Wc, const float* __restrict__ Wd,
                            const float* __restrict__ We) {
    int idx = blockIdx.x * blockDim.x + threadIdx.x;
    if (idx < 5 * 16384) {
        int mm = idx >> 14;
        int rem = idx & 16383;
        int n = rem >> 7, k = rem & 127;
        const float* W = (mm == 0) ? Wa : (mm == 1) ? Wb : (mm == 2) ? Wc : (mm == 3) ? Wd : We;
        float v = W[k * DD + n];                 // transpose: Wt[n][k] = W[k][n]
        *(__half*)(g_Wh + mm * 32768 + bsw(n, k)) = __float2half_rn(v);
    }
}

__global__ void zero_kernel(int Nn) {
    int idx = blockIdx.x * blockDim.x + threadIdx.x;   // float4 index
    int total = Nn * (DD / 4);
    if (idx < total) {
        float4 z = make_float4(0.f, 0.f, 0.f, 0.f);
        ((float4*)g_num)[idx] = z;
        ((float4*)g_den)[idx] = z;
    }
}

// ---------------- node GEMMs: out_y = (h*norm)@W_y + bias ----------------
__global__ __launch_bounds__(256, 2) void node_mma_kernel(
        const float* __restrict__ h, const float* __restrict__ norm,
        const float* __restrict__ ba, const float* __restrict__ bb,
        const float* __restrict__ bd, const float* __restrict__ be,
        const float* __restrict__ bc, int M) {
    extern __shared__ unsigned char sm[];
    int tid = threadIdx.x;
    int y = blockIdx.y;
    int widx = (y == 0) ? 0 : (y == 1) ? 1 : (y == 2) ? 3 : 4;   // a,b,d,e
    float* out        = (y == 0) ? g_Ah : (y == 1) ? g_Bh : (y == 2) ? g_Dh : g_Eh;
    const float* bias = (y == 0) ? ba   : (y == 1) ? bb   : (y == 2) ? bd   : be;
    const float* bias2 = (y == 2) ? bc : nullptr;     // fold bc into Dh
    int row0 = blockIdx.x * 128;

    {
        const uint4* s = (const uint4*)(g_Wh + widx * 32768);
        uint4* d = (uint4*)(sm + NSM_W);
        #pragma unroll
        for (int i = tid; i < 2048; i += 256) d[i] = __ldg(s + i);
    }
    load_convert_A<true>(h, norm, row0, M, sm + NSM_A);
    __syncthreads();

    int lane = tid & 31, w = tid >> 5;
    int rbase = row0 + w * 16 + (lane >> 2);
    int cp = 2 * (lane & 3);

    #pragma unroll
    for (int half = 0; half < 2; half++) {
        float acc[8][4];
        gemm_fp16_half(sm + NSM_A, sm + NSM_W, half, acc);
        #pragma unroll
        for (int n8 = 0; n8 < 8; n8++) {
            int c = half * 64 + n8 * 8 + cp;
            float2 bv = __ldg((const float2*)(bias + c));
            if (bias2) {
                float2 b2 = __ldg((const float2*)(bias2 + c));
                bv.x += b2.x; bv.y += b2.y;
            }
            if (rbase < M)
                *(float2*)(out + (size_t)rbase * DD + c) =
                    make_float2(acc[n8][0] + bv.x, acc[n8][1] + bv.y);
            if (rbase + 8 < M)
                *(float2*)(out + (size_t)(rbase + 8) * DD + c) =
                    make_float2(acc[n8][2] + bv.x, acc[n8][3] + bv.y);
        }
    }
}

// ---------------- edge kernel: one 128-edge tile per CTA, epilogue from fragments ----------------
__global__ __launch_bounds__(256, 3) void edge_mma_kernel(
        const float* __restrict__ e,
        const int* __restrict__ src, const int* __restrict__ dst,
        float* __restrict__ out_e, int E) {
    extern __shared__ unsigned char sm[];
    int tid = threadIdx.x;
    int tile = blockIdx.x;

    {   // Wc (index 2)
        const uint4* s = (const uint4*)(g_Wh + 2 * 32768);
        uint4* d = (uint4*)(sm + ESM_W);
        #pragma unroll
        for (int i = tid; i < 2048; i += 256) d[i] = __ldg(s + i);
    }
    load_convert_A<false>(e, nullptr, tile * 128, E, sm + ESM_A);
    __syncthreads();

    int lane = tid & 31, w = tid >> 5;
    int rbase = w * 16 + (lane >> 2);
    int cp = 2 * (lane & 3);

    #pragma unroll
    for (int half = 0; half < 2; half++) {
        float acc[8][4];
        gemm_fp16_half(sm + ESM_A, sm + ESM_W, half, acc);

        #pragma unroll
        for (int rr = 0; rr < 2; rr++) {
            int er = tile * 128 + rbase + rr * 8;
            if (er < E) {
                int s = __ldg(src + er);
                int d = __ldg(dst + er);
                const float* Dhp = g_Dh + (size_t)s * DD;   // includes bc + bd
                const float* Ehp = g_Eh + (size_t)d * DD;
                const float* Bhp = g_Bh + (size_t)s * DD;
                float* nup = g_num + (size_t)d * DD;
                float* dep = g_den + (size_t)d * DD;
                float* eop = out_e + (size_t)er * DD;
                #pragma unroll
                for (int n8 = 0; n8 < 8; n8++) {
                    int c = half * 64 + n8 * 8 + cp;
                    float2 dh = __ldg((const float2*)(Dhp + c));
                    float2 eh = __ldg((const float2*)(Ehp + c));
                    float x0 = acc[n8][rr * 2 + 0] + dh.x + eh.x;
                    float x1 = acc[n8][rr * 2 + 1] + dh.y + eh.y;
                    *(float2*)(eop + c) = make_float2(x0, x1);
                    float2 bh = __ldg((const float2*)(Bhp + c));
                    float s0 = __fdividef(1.f, 1.f + __expf(-x0));
                    float s1 = __fdividef(1.f, 1.f + __expf(-x1));
                    red_add_v2(nup + c, s0 * bh.x, s1 * bh.y);
                    red_add_v2(dep + c, s0, s1);
                }
            }
        }
    }
}

// ---------------- finalize (deg>0 <=> den>0, sigmoids strictly positive) ----------------
__global__ void finalize_kernel(const float* __restrict__ h,
                                const float* __restrict__ norm,
                                float* __restrict__ out_h, int Nn) {
    int idx = blockIdx.x * blockDim.x + threadIdx.x;   // float4 index
    int total = Nn * (DD / 4);
    if (idx >= total) return;
    int node = idx >> 5;
    float nm = __ldg(norm + node);
    float4 de = ((const float4*)g_den)[idx];
    float4 r;
    if (de.x > 0.f) {
        float4 a  = ((const float4*)g_Ah)[idx];
        float4 nu = ((const float4*)g_num)[idx];
        r.x = (a.x + nu.x / (de.x + 1e-6f)) * nm;
        r.y = (a.y + nu.y / (de.y + 1e-6f)) * nm;
        r.z = (a.z + nu.z / (de.z + 1e-6f)) * nm;
        r.w = (a.w + nu.w / (de.w + 1e-6f)) * nm;
    } else {
        float4 hh = *(const float4*)(h + (size_t)idx * 4);
        float sc = nm * nm;
        r = make_float4(hh.x * sc, hh.y * sc, hh.z * sc, hh.w * sc);
    }
    ((float4*)out_h)[idx] = r;
}

// ---------------- launch ----------------
extern "C" void kernel_launch(void* const* d_in, const int* in_sizes, int n_in,
                              void* d_out, int out_size) {
    const float* h    = (const float*)d_in[0];
    const float* e    = (const float*)d_in[1];
    const float* norm = (const float*)d_in[2];
    const int*   src  = (const int*)d_in[3];
    const int*   dst  = (const int*)d_in[4];
    const float* Wa = (const float*)d_in[5],  *ba = (const float*)d_in[6];
    const float* Wb = (const float*)d_in[7],  *bb = (const float*)d_in[8];
    const float* Wc = (const float*)d_in[9],  *bc = (const float*)d_in[10];
    const float* Wd = (const float*)d_in[11], *bd = (const float*)d_in[12];
    const float* We = (const float*)d_in[13], *be = (const float*)d_in[14];

    int Nn = in_sizes[0] / DD;   // 40000
    int Ee = in_sizes[3];        // 600000

    float* out_h = (float*)d_out;
    float* out_e = out_h + (size_t)Nn * DD;

    cudaFuncSetAttribute(node_mma_kernel, cudaFuncAttributeMaxDynamicSharedMemorySize, NSM_REQ);
    cudaFuncSetAttribute(edge_mma_kernel, cudaFuncAttributeMaxDynamicSharedMemorySize, ESM_REQ);

    // launch order chosen so the edge kernel is the 4th launch (ncu captures #4)
    prep_kernel<<<(5 * 16384 + 255) / 256, 256>>>(Wa, Wb, Wc, Wd, We);

    zero_kernel<<<(Nn * (DD / 4) + 255) / 256, 256>>>(Nn);

    dim3 ngrid((Nn + 127) / 128, 4);
    node_mma_kernel<<<ngrid, 256, NSM_REQ>>>(h, norm, ba, bb, bd, be, bc, Nn);

    edge_mma_kernel<<<(Ee + 127) / 128, 256, ESM_REQ>>>(e, src, dst, out_e, Ee);

    finalize_kernel<<<(Nn * (DD / 4) + 255) / 256, 256>>>(h, norm, out_h, Nn);
}